// round 1
// baseline (speedup 1.0000x reference)
#include <cuda_runtime.h>
#include <cstdint>

#define R_TOT 8192     // B*S
#define D_DIM 1024
#define V_DIM 16384

#define BM 64
#define BN 128
#define BK 16

// -------- device scratch (no allocations allowed) --------
__device__ float g_inv_x[R_TOT];
__device__ float g_inv_d[V_DIM];
__device__ unsigned long long g_best[R_TOT];
__device__ float g_eln[(size_t)R_TOT * D_DIM];   // 32 MB

// -------- row inverse L2 norms --------
__global__ void rownorm_kernel(const float* __restrict__ src, int which) {
    int row = blockIdx.x;
    const float* p = src + (size_t)row * D_DIM;
    float s = 0.f;
    for (int j = threadIdx.x; j < D_DIM; j += blockDim.x) { float v = p[j]; s += v * v; }
    __shared__ float red[32];
    #pragma unroll
    for (int o = 16; o; o >>= 1) s += __shfl_down_sync(0xffffffffu, s, o);
    int lane = threadIdx.x & 31, wid = threadIdx.x >> 5;
    if (lane == 0) red[wid] = s;
    __syncthreads();
    if (wid == 0) {
        s = (lane < (int)(blockDim.x >> 5)) ? red[lane] : 0.f;
        #pragma unroll
        for (int o = 4; o; o >>= 1) s += __shfl_down_sync(0xffffffffu, s, o);
        if (lane == 0) {
            float inv = 1.0f / sqrtf(fmaxf(s, 1e-12f));
            if (which == 0) g_inv_x[row] = inv; else g_inv_d[row] = inv;
        }
    }
}

__global__ void init_best_kernel() {
    int i = blockIdx.x * blockDim.x + threadIdx.x;
    if (i < R_TOT) g_best[i] = 0ULL;
}

// -------- fused sim-GEMM + per-row argmax (fp32, NT) --------
__global__ void __launch_bounds__(128)
simgemm_kernel(const float* __restrict__ X, const float* __restrict__ Dw) {
    __shared__ float As[BK][BM + 4];
    __shared__ float Bs[BK][BN + 4];
    __shared__ float sv[BM][16];
    __shared__ int   si[BM][16];

    int tid = threadIdx.x;
    int ty = tid >> 4, tx = tid & 15;
    int rb = blockIdx.x * BM;
    int colsPer = V_DIM / gridDim.y;
    int cbeg = blockIdx.y * colsPer;

    float inva[8];
    #pragma unroll
    for (int i = 0; i < 8; i++) inva[i] = g_inv_x[rb + ty * 8 + i];

    float bestv[8]; int bidx[8];
    #pragma unroll
    for (int i = 0; i < 8; i++) { bestv[i] = -2.0f; bidx[i] = 0; }

    int ar = tid >> 2;
    int ak = (tid & 3) << 2;

    for (int c0 = cbeg; c0 < cbeg + colsPer; c0 += BN) {
        float acc[8][8];
        #pragma unroll
        for (int i = 0; i < 8; i++)
            #pragma unroll
            for (int j = 0; j < 8; j++) acc[i][j] = 0.f;

        for (int k0 = 0; k0 < D_DIM; k0 += BK) {
            #pragma unroll
            for (int m = 0; m < BM; m += 32) {
                float4 v = *(const float4*)(X + (size_t)(rb + ar + m) * D_DIM + k0 + ak);
                As[ak + 0][ar + m] = v.x; As[ak + 1][ar + m] = v.y;
                As[ak + 2][ar + m] = v.z; As[ak + 3][ar + m] = v.w;
            }
            #pragma unroll
            for (int n = 0; n < BN; n += 32) {
                float4 v = *(const float4*)(Dw + (size_t)(c0 + ar + n) * D_DIM + k0 + ak);
                Bs[ak + 0][ar + n] = v.x; Bs[ak + 1][ar + n] = v.y;
                Bs[ak + 2][ar + n] = v.z; Bs[ak + 3][ar + n] = v.w;
            }
            __syncthreads();
            #pragma unroll
            for (int k = 0; k < BK; k++) {
                float a[8], b[8];
                *(float4*)(a)     = *(const float4*)(&As[k][ty * 8]);
                *(float4*)(a + 4) = *(const float4*)(&As[k][ty * 8 + 4]);
                *(float4*)(b)     = *(const float4*)(&Bs[k][tx * 8]);
                *(float4*)(b + 4) = *(const float4*)(&Bs[k][tx * 8 + 4]);
                #pragma unroll
                for (int i = 0; i < 8; i++)
                    #pragma unroll
                    for (int j = 0; j < 8; j++)
                        acc[i][j] = fmaf(a[i], b[j], acc[i][j]);
            }
            __syncthreads();
        }
        float invb[8];
        #pragma unroll
        for (int j = 0; j < 8; j++) invb[j] = g_inv_d[c0 + tx * 8 + j];
        #pragma unroll
        for (int i = 0; i < 8; i++) {
            #pragma unroll
            for (int j = 0; j < 8; j++) {
                float s = acc[i][j] * inva[i] * invb[j];
                int col = c0 + tx * 8 + j;
                if (s > bestv[i]) { bestv[i] = s; bidx[i] = col; }
            }
        }
    }

    #pragma unroll
    for (int i = 0; i < 8; i++) { sv[ty * 8 + i][tx] = bestv[i]; si[ty * 8 + i][tx] = bidx[i]; }
    __syncthreads();
    if (tid < BM) {
        float bv = -3.f; int bi = 0x7FFFFFFF;
        #pragma unroll
        for (int t = 0; t < 16; t++) {
            float v = sv[tid][t]; int ix = si[tid][t];
            if (v > bv || (v == bv && ix < bi)) { bv = v; bi = ix; }
        }
        unsigned fb = __float_as_uint(bv);
        unsigned key = (fb & 0x80000000u) ? ~fb : (fb | 0x80000000u);
        unsigned long long packed = ((unsigned long long)key << 32) | (unsigned)(~(unsigned)bi);
        atomicMax(&g_best[rb + tid], packed);
    }
}

// -------- block sum helper (blockDim == 256) --------
__device__ __forceinline__ float block_sum_256(float v, float* red) {
    #pragma unroll
    for (int o = 16; o; o >>= 1) v += __shfl_down_sync(0xffffffffu, v, o);
    int lane = threadIdx.x & 31, wid = threadIdx.x >> 5;
    __syncthreads();
    if (lane == 0) red[wid] = v;
    __syncthreads();
    float t = (threadIdx.x < 8) ? red[threadIdx.x] : 0.f;
    if (wid == 0) {
        #pragma unroll
        for (int o = 4; o; o >>= 1) t += __shfl_down_sync(0xffffffffu, t, o);
        if (lane == 0) red[0] = t;
    }
    __syncthreads();
    return red[0];
}

// -------- decode winner, write idx/sim, gather + STE + LayerNorm --------
__global__ void ln_kernel(const float* __restrict__ X, const float* __restrict__ Dw,
                          const float* __restrict__ gamma, const float* __restrict__ beta,
                          float* __restrict__ out, int write_aux, int sim_off) {
    int row = blockIdx.x;
    __shared__ float red[32];
    __shared__ int s_idx;
    if (threadIdx.x == 0) {
        unsigned long long p = g_best[row];
        unsigned hi = (unsigned)(p >> 32);
        unsigned lo = (unsigned)p;
        int idx = (int)(~lo);
        unsigned fb = (hi & 0x80000000u) ? (hi & 0x7FFFFFFFu) : ~hi;
        float val = __uint_as_float(fb);
        s_idx = idx;
        if (write_aux) {
            out[row] = (float)idx;       // word_idx region (as f32 value)
            out[sim_off + row] = val;    // word_sim region
        }
    }
    __syncthreads();
    int idx = s_idx;
    const float* xr = X + (size_t)row * D_DIM;
    const float* zr = Dw + (size_t)idx * D_DIM;
    int tid = threadIdx.x;
    float ev[4];
    float s = 0.f;
    #pragma unroll
    for (int t = 0; t < 4; t++) {
        int j = t * 256 + tid;
        float xv = xr[j], zv = zr[j];
        ev[t] = (zv - xv) + xv;          // exact STE forward rounding
        s += ev[t];
    }
    float mu = block_sum_256(s, red) * (1.0f / D_DIM);
    float ss = 0.f;
    #pragma unroll
    for (int t = 0; t < 4; t++) { float d = ev[t] - mu; ss += d * d; }
    float var = block_sum_256(ss, red) * (1.0f / D_DIM);
    float rsig = 1.0f / sqrtf(var + 1e-6f);
    #pragma unroll
    for (int t = 0; t < 4; t++) {
        int j = t * 256 + tid;
        g_eln[(size_t)row * D_DIM + j] = (ev[t] - mu) * rsig * gamma[j] + beta[j];
    }
}

// -------- output projection GEMM (NN): out = e_ln @ o_w --------
__global__ void __launch_bounds__(128)
outgemm_kernel(const float* __restrict__ Ow, float* __restrict__ Out) {
    __shared__ float As[BK][BM + 4];
    __shared__ float Bs[BK][BN + 4];
    int tid = threadIdx.x;
    int ty = tid >> 4, tx = tid & 15;
    int rb = blockIdx.x * BM;
    int nb = blockIdx.y * BN;
    float acc[8][8];
    #pragma unroll
    for (int i = 0; i < 8; i++)
        #pragma unroll
        for (int j = 0; j < 8; j++) acc[i][j] = 0.f;

    int ar = tid >> 2;
    int ak = (tid & 3) << 2;
    int bk = tid >> 3;          // 0..15
    int bn = (tid & 7) << 4;    // 0..112

    for (int k0 = 0; k0 < D_DIM; k0 += BK) {
        #pragma unroll
        for (int m = 0; m < BM; m += 32) {
            float4 v = *(const float4*)(g_eln + (size_t)(rb + ar + m) * D_DIM + k0 + ak);
            As[ak + 0][ar + m] = v.x; As[ak + 1][ar + m] = v.y;
            As[ak + 2][ar + m] = v.z; As[ak + 3][ar + m] = v.w;
        }
        #pragma unroll
        for (int c = 0; c < 16; c += 4) {
            float4 v = *(const float4*)(Ow + (size_t)(k0 + bk) * D_DIM + nb + bn + c);
            *(float4*)(&Bs[bk][bn + c]) = v;
        }
        __syncthreads();
        #pragma unroll
        for (int k = 0; k < BK; k++) {
            float a[8], b[8];
            *(float4*)(a)     = *(const float4*)(&As[k][ty * 8]);
            *(float4*)(a + 4) = *(const float4*)(&As[k][ty * 8 + 4]);
            *(float4*)(b)     = *(const float4*)(&Bs[k][tx * 8]);
            *(float4*)(b + 4) = *(const float4*)(&Bs[k][tx * 8 + 4]);
            #pragma unroll
            for (int i = 0; i < 8; i++)
                #pragma unroll
                for (int j = 0; j < 8; j++)
                    acc[i][j] = fmaf(a[i], b[j], acc[i][j]);
        }
        __syncthreads();
    }
    #pragma unroll
    for (int i = 0; i < 8; i++) {
        float4 v0 = make_float4(acc[i][0], acc[i][1], acc[i][2], acc[i][3]);
        float4 v1 = make_float4(acc[i][4], acc[i][5], acc[i][6], acc[i][7]);
        float* dst = Out + (size_t)(rb + ty * 8 + i) * D_DIM + nb + tx * 8;
        *(float4*)(dst)     = v0;
        *(float4*)(dst + 4) = v1;
    }
}

extern "C" void kernel_launch(void* const* d_in, const int* in_sizes, int n_in,
                              void* d_out, int out_size) {
    const float* x     = (const float*)d_in[0];
    const float* dw    = (const float*)d_in[1];
    const float* gamma = (const float*)d_in[2];
    const float* beta  = (const float*)d_in[3];
    const float* ow    = (const float*)d_in[4];
    float* out = (float*)d_out;

    const int out_elems = R_TOT * D_DIM;                       // 8388608
    int write_aux = (out_size >= out_elems + 2 * R_TOT) ? 1 : 0;
    size_t out_off = write_aux ? (size_t)(2 * R_TOT) : 0;

    rownorm_kernel<<<R_TOT, 256>>>(x, 0);
    rownorm_kernel<<<V_DIM, 256>>>(dw, 1);
    init_best_kernel<<<(R_TOT + 255) / 256, 256>>>();
    simgemm_kernel<<<dim3(R_TOT / BM, 4), 128>>>(x, dw);
    ln_kernel<<<R_TOT, 256>>>(x, dw, gamma, beta, out, write_aux, R_TOT);
    outgemm_kernel<<<dim3(R_TOT / BM, D_DIM / BN), 128>>>(ow, out + out_off);
}

// round 7
// speedup vs baseline: 5.4080x; 5.4080x over previous
#include <cuda_runtime.h>
#include <cuda_bf16.h>
#include <cstdint>

#define R_TOT 8192     // B*S
#define D_DIM 1024
#define V_DIM 16384
#define NSPLIT 8       // V splits (grid.y)
#define NCAND 16       // candidate slots per row: 8 splits x 2 warp-halves

// ---------------- device scratch ----------------
__device__ float g_inv_x[R_TOT];
__device__ float g_inv_d[V_DIM];
__device__ __nv_bfloat16 g_qbf[(size_t)R_TOT * D_DIM];   // normalized x, bf16
__device__ __nv_bfloat16 g_kbf[(size_t)V_DIM * D_DIM];   // normalized dict, bf16
__device__ float g_cv[R_TOT][NCAND][2];
__device__ int   g_ci[R_TOT][NCAND][2];
__device__ int   g_widx[R_TOT];
__device__ float g_eln[(size_t)R_TOT * D_DIM];           // 32 MB

__device__ __forceinline__ uint32_t smem_u32(const void* p) {
    uint32_t a;
    asm("{ .reg .u64 t; cvta.to.shared.u64 t, %1; cvt.u32.u64 %0, t; }" : "=r"(a) : "l"(p));
    return a;
}

// ---------------- block reduce (256 threads) ----------------
__device__ __forceinline__ float block_sum_256(float v, float* red) {
    #pragma unroll
    for (int o = 16; o; o >>= 1) v += __shfl_down_sync(0xffffffffu, v, o);
    int lane = threadIdx.x & 31, wid = threadIdx.x >> 5;
    __syncthreads();
    if (lane == 0) red[wid] = v;
    __syncthreads();
    float t = (threadIdx.x < 8) ? red[threadIdx.x] : 0.f;
    if (wid == 0) {
        #pragma unroll
        for (int o = 4; o; o >>= 1) t += __shfl_down_sync(0xffffffffu, t, o);
        if (lane == 0) red[0] = t;
    }
    __syncthreads();
    return red[0];
}

// ---------------- L2-normalize + bf16 convert ----------------
__global__ void norm_convert_kernel(const float* __restrict__ src, int which) {
    int row = blockIdx.x;
    const float* p = src + (size_t)row * D_DIM;
    int tid = threadIdx.x;
    float4 v = *(const float4*)(p + tid * 4);
    float s = v.x * v.x + v.y * v.y + v.z * v.z + v.w * v.w;
    __shared__ float red[32];
    float ss = block_sum_256(s, red);
    float inv = rsqrtf(fmaxf(ss, 1e-12f));
    __nv_bfloat16* dst = (which == 0 ? g_qbf : g_kbf) + (size_t)row * D_DIM + tid * 4;
    __nv_bfloat162 a = __floats2bfloat162_rn(v.x * inv, v.y * inv);
    __nv_bfloat162 b = __floats2bfloat162_rn(v.z * inv, v.w * inv);
    *(__nv_bfloat162*)(dst)     = a;
    *(__nv_bfloat162*)(dst + 2) = b;
    if (tid == 0) { if (which == 0) g_inv_x[row] = inv; else g_inv_d[row] = inv; }
}

// ---------------- bf16 mma.sync sim-GEMM + per-row top-2 ----------------
// CTA tile 128(M) x 128(N), K streamed in 64-wide bf16 chunks, 2-stage cp.async.
// 8 warps in 4x2: warp tile 32(M) x 64(N). grid (64 m-tiles, 8 v-splits),
// each CTA loops 16 n-tiles (2048 cols per split).
#define STAGE_B 32768           // A 16KB + B 16KB
#define SIM_SMEM (2 * STAGE_B)

#define CPA16(dst, src) \
    asm volatile("cp.async.cg.shared.global [%0], [%1], 16;" :: "r"(dst), "l"(src))
#define CPA_COMMIT() asm volatile("cp.async.commit_group;" ::: "memory")

#define LDMX4(r0, r1, r2, r3, addr) \
    asm volatile("ldmatrix.sync.aligned.m8n8.x4.shared.b16 {%0,%1,%2,%3}, [%4];" \
        : "=r"(r0), "=r"(r1), "=r"(r2), "=r"(r3) : "r"(addr))

#define MMA16816(d, a, b0, b1) \
    asm volatile("mma.sync.aligned.m16n8k16.row.col.f32.bf16.bf16.f32 " \
        "{%0,%1,%2,%3}, {%4,%5,%6,%7}, {%8,%9}, {%0,%1,%2,%3};" \
        : "+f"((d)[0]), "+f"((d)[1]), "+f"((d)[2]), "+f"((d)[3]) \
        : "r"((a)[0]), "r"((a)[1]), "r"((a)[2]), "r"((a)[3]), "r"(b0), "r"(b1))

#define INSERT(q, v, ix) do { \
    if ((v) > tv1[q] || ((v) == tv1[q] && (ix) < ti1[q])) { \
        tv2[q] = tv1[q]; ti2[q] = ti1[q]; tv1[q] = (v); ti1[q] = (ix); \
    } else if ((v) > tv2[q] || ((v) == tv2[q] && (ix) < ti2[q])) { \
        tv2[q] = (v); ti2[q] = (ix); \
    } } while (0)

__global__ void __launch_bounds__(256, 1)
simmma_kernel() {
    extern __shared__ char sm[];
    uint32_t sb = smem_u32(sm);
    const int tid = threadIdx.x, lane = tid & 31, w = tid >> 5;
    const int wm = (w & 3) * 32, wn = (w >> 2) * 64;
    const int rb = blockIdx.x * 128;
    const int cb = blockIdx.y * 2048;

    // per-thread global->smem mapping (4 x 16B per operand per chunk)
    int lrow[4], lkg[4]; uint32_t ldst[4];
    #pragma unroll
    for (int i = 0; i < 4; i++) {
        int u = tid + i * 256;
        lrow[i] = u >> 3; lkg[i] = u & 7;
        ldst[i] = (uint32_t)(lrow[i] * 128 + ((lkg[i] ^ (lrow[i] & 7)) << 4));
    }

    // ldmatrix smem offsets (within a stage)
    int a_row[2], b_row[4]; int a_kgb, b_kgb;
    {
        int g = lane >> 4;             // A: which k8 half
        a_kgb = g;                     // + ks*2
        a_row[0] = wm + (lane & 15);
        a_row[1] = wm + 16 + (lane & 15);
        int bg = lane >> 3;            // B: 4 groups of 8 lanes
        b_kgb = bg & 1;                // + ks*2
        #pragma unroll
        for (int p = 0; p < 4; p++)
            b_row[p] = wn + (p * 2 + (bg >> 1)) * 8 + (lane & 7);
    }

    float tv1[4], tv2[4]; int ti1[4], ti2[4];
    #pragma unroll
    for (int q = 0; q < 4; q++) { tv1[q] = -2.f; tv2[q] = -2.f; ti1[q] = 0; ti2[q] = 0; }

    for (int nt = 0; nt < 16; nt++) {
        const __nv_bfloat16* Bsrc = g_kbf + (size_t)(cb + nt * 128) * D_DIM;

        // preload chunks 0 and 1
        #pragma unroll
        for (int pc = 0; pc < 2; pc++) {
            uint32_t stg = sb + pc * STAGE_B;
            #pragma unroll
            for (int i = 0; i < 4; i++) {
                const __nv_bfloat16* as = g_qbf + (size_t)(rb + lrow[i]) * D_DIM + pc * 64 + lkg[i] * 8;
                const __nv_bfloat16* bs = Bsrc + (size_t)lrow[i] * D_DIM + pc * 64 + lkg[i] * 8;
                CPA16(stg + ldst[i], as);
                CPA16(stg + 16384 + ldst[i], bs);
            }
            CPA_COMMIT();
        }

        float acc[2][8][4];
        #pragma unroll
        for (int mt = 0; mt < 2; mt++)
            #pragma unroll
            for (int j = 0; j < 8; j++)
                #pragma unroll
                for (int c = 0; c < 4; c++) acc[mt][j][c] = 0.f;

        for (int kc = 0; kc < 16; kc++) {
            if (kc >= 14) asm volatile("cp.async.wait_group 0;" ::: "memory");
            else          asm volatile("cp.async.wait_group 1;" ::: "memory");
            __syncthreads();

            uint32_t aS = sb + (kc & 1) * STAGE_B;
            uint32_t bS = aS + 16384;
            #pragma unroll
            for (int ks = 0; ks < 4; ks++) {
                uint32_t a[2][4];
                #pragma unroll
                for (int mt = 0; mt < 2; mt++) {
                    int kg = ks * 2 + a_kgb;
                    uint32_t addr = aS + a_row[mt] * 128 + ((kg ^ (a_row[mt] & 7)) << 4);
                    LDMX4(a[mt][0], a[mt][1], a[mt][2], a[mt][3], addr);
                }
                #pragma unroll
                for (int p = 0; p < 4; p++) {
                    uint32_t b[4];
                    int kg = ks * 2 + b_kgb;
                    uint32_t addr = bS + b_row[p] * 128 + ((kg ^ (b_row[p] & 7)) << 4);
                    LDMX4(b[0], b[1], b[2], b[3], addr);
                    #pragma unroll
                    for (int mt = 0; mt < 2; mt++) {
                        MMA16816(acc[mt][p * 2 + 0], a[mt], b[0], b[1]);
                        MMA16816(acc[mt][p * 2 + 1], a[mt], b[2], b[3]);
                    }
                }
            }
            __syncthreads();
            if (kc + 2 < 16) {
                uint32_t stg = sb + (kc & 1) * STAGE_B;
                int kcn = kc + 2;
                #pragma unroll
                for (int i = 0; i < 4; i++) {
                    const __nv_bfloat16* as = g_qbf + (size_t)(rb + lrow[i]) * D_DIM + kcn * 64 + lkg[i] * 8;
                    const __nv_bfloat16* bs = Bsrc + (size_t)lrow[i] * D_DIM + kcn * 64 + lkg[i] * 8;
                    CPA16(stg + ldst[i], as);
                    CPA16(stg + 16384 + ldst[i], bs);
                }
                CPA_COMMIT();
            }
        }

        // top-2 update from accumulators
        int colbase = cb + nt * 128 + wn + (lane & 3) * 2;
        #pragma unroll
        for (int mt = 0; mt < 2; mt++)
            #pragma unroll
            for (int h = 0; h < 2; h++) {
                int q = mt * 2 + h;
                #pragma unroll
                for (int j = 0; j < 8; j++) {
                    float v0 = acc[mt][j][h * 2 + 0];
                    float v1 = acc[mt][j][h * 2 + 1];
                    int c0 = colbase + j * 8;
                    INSERT(q, v0, c0);
                    INSERT(q, v1, c0 + 1);
                }
            }
    }

    // merge top-2 across the 4 lanes of each quad (same rows, different cols)
    #pragma unroll
    for (int off = 1; off <= 2; off <<= 1) {
        #pragma unroll
        for (int q = 0; q < 4; q++) {
            float ov1 = __shfl_xor_sync(0xffffffffu, tv1[q], off);
            int   oi1 = __shfl_xor_sync(0xffffffffu, ti1[q], off);
            float ov2 = __shfl_xor_sync(0xffffffffu, tv2[q], off);
            int   oi2 = __shfl_xor_sync(0xffffffffu, ti2[q], off);
            INSERT(q, ov1, oi1);
            INSERT(q, ov2, oi2);
        }
    }
    if ((lane & 3) == 0) {
        int slot = blockIdx.y * 2 + (w >> 2);
        #pragma unroll
        for (int q = 0; q < 4; q++) {
            int row = rb + wm + (q >> 1) * 16 + (q & 1) * 8 + (lane >> 2);
            g_cv[row][slot][0] = tv1[q]; g_ci[row][slot][0] = ti1[q];
            g_cv[row][slot][1] = tv2[q]; g_ci[row][slot][1] = ti2[q];
        }
    }
}

// ---------------- exact fp32 rescore of candidates ----------------
__global__ void rescore_kernel(const float* __restrict__ X, const float* __restrict__ Dw,
                               float* __restrict__ out, int write_aux) {
    int row = blockIdx.x;
    int tid = threadIdx.x;
    __shared__ float sv[32]; __shared__ int si[32];
    __shared__ float red[32];
    __shared__ float s_vmax, s_best; __shared__ int s_bidx;
    if (tid < 32) { sv[tid] = g_cv[row][tid >> 1][tid & 1]; si[tid] = g_ci[row][tid >> 1][tid & 1]; }
    __syncthreads();
    if (tid == 0) {
        float vm = -9.f;
        for (int t = 0; t < 32; t++) vm = fmaxf(vm, sv[t]);
        s_vmax = vm; s_best = -9.f; s_bidx = 0x7FFFFFFF;
    }
    __syncthreads();
    float inva = g_inv_x[row];
    const float4* xr = (const float4*)(X + (size_t)row * D_DIM);
    float4 xv = xr[tid];
    for (int c = 0; c < 32; c++) {
        if (sv[c] < s_vmax - 1e-3f) continue;
        int idx = si[c];
        const float4* dr = (const float4*)(Dw + (size_t)idx * D_DIM);
        float4 dv = dr[tid];
        float part = xv.x * dv.x + xv.y * dv.y + xv.z * dv.z + xv.w * dv.w;
        float tot = block_sum_256(part, red);
        if (tid == 0) {
            float sim = tot * inva * g_inv_d[idx];
            if (sim > s_best || (sim == s_best && idx < s_bidx)) { s_best = sim; s_bidx = idx; }
        }
        __syncthreads();
    }
    if (tid == 0) {
        g_widx[row] = s_bidx;
        if (write_aux) { out[row] = (float)s_bidx; out[R_TOT + row] = s_best; }
    }
}

// ---------------- STE + LayerNorm ----------------
__global__ void ln_kernel(const float* __restrict__ X, const float* __restrict__ Dw,
                          const float* __restrict__ gamma, const float* __restrict__ beta) {
    int row = blockIdx.x;
    __shared__ float red[32];
    int idx = g_widx[row];
    const float* xr = X + (size_t)row * D_DIM;
    const float* zr = Dw + (size_t)idx * D_DIM;
    int tid = threadIdx.x;
    float ev[4];
    float s = 0.f;
    #pragma unroll
    for (int t = 0; t < 4; t++) {
        int j = t * 256 + tid;
        float xv = xr[j], zv = zr[j];
        ev[t] = (zv - xv) + xv;
        s += ev[t];
    }
    float mu = block_sum_256(s, red) * (1.0f / D_DIM);
    float ss = 0.f;
    #pragma unroll
    for (int t = 0; t < 4; t++) { float d = ev[t] - mu; ss += d * d; }
    float var = block_sum_256(ss, red) * (1.0f / D_DIM);
    float rsig = rsqrtf(var + 1e-6f);
    #pragma unroll
    for (int t = 0; t < 4; t++) {
        int j = t * 256 + tid;
        g_eln[(size_t)row * D_DIM + j] = (ev[t] - mu) * rsig * gamma[j] + beta[j];
    }
}

// ---------------- output projection (fp32 SIMT) ----------------
#define BM 64
#define BN 128
#define BK 16
__global__ void __launch_bounds__(128)
outgemm_kernel(const float* __restrict__ Ow, float* __restrict__ Out) {
    __shared__ float As[BK][BM + 4];
    __shared__ float Bs[BK][BN + 4];
    int tid = threadIdx.x;
    int ty = tid >> 4, tx = tid & 15;
    int rb = blockIdx.x * BM;
    int nb = blockIdx.y * BN;
    float acc[8][8];
    #pragma unroll
    for (int i = 0; i < 8; i++)
        #pragma unroll
        for (int j = 0; j < 8; j++) acc[i][j] = 0.f;

    int ar = tid >> 2;
    int ak = (tid & 3) << 2;
    int bk = tid >> 3;
    int bn = (tid & 7) << 4;

    for (int k0 = 0; k0 < D_DIM; k0 += BK) {
        #pragma unroll
        for (int m = 0; m < BM; m += 32) {
            float4 v = *(const float4*)(g_eln + (size_t)(rb + ar + m) * D_DIM + k0 + ak);
            As[ak + 0][ar + m] = v.x; As[ak + 1][ar + m] = v.y;
            As[ak + 2][ar + m] = v.z; As[ak + 3][ar + m] = v.w;
        }
        #pragma unroll
        for (int c = 0; c < 16; c += 4) {
            float4 v = *(const float4*)(Ow + (size_t)(k0 + bk) * D_DIM + nb + bn + c);
            *(float4*)(&Bs[bk][bn + c]) = v;
        }
        __syncthreads();
        #pragma unroll
        for (int k = 0; k < BK; k++) {
            float a[8], b[8];
            *(float4*)(a)     = *(const float4*)(&As[k][ty * 8]);
            *(float4*)(a + 4) = *(const float4*)(&As[k][ty * 8 + 4]);
            *(float4*)(b)     = *(const float4*)(&Bs[k][tx * 8]);
            *(float4*)(b + 4) = *(const float4*)(&Bs[k][tx * 8 + 4]);
            #pragma unroll
            for (int i = 0; i < 8; i++)
                #pragma unroll
                for (int j = 0; j < 8; j++)
                    acc[i][j] = fmaf(a[i], b[j], acc[i][j]);
        }
        __syncthreads();
    }
    #pragma unroll
    for (int i = 0; i < 8; i++) {
        float4 v0 = make_float4(acc[i][0], acc[i][1], acc[i][2], acc[i][3]);
        float4 v1 = make_float4(acc[i][4], acc[i][5], acc[i][6], acc[i][7]);
        float* dst = Out + (size_t)(rb + ty * 8 + i) * D_DIM + nb + tx * 8;
        *(float4*)(dst)     = v0;
        *(float4*)(dst + 4) = v1;
    }
}

extern "C" void kernel_launch(void* const* d_in, const int* in_sizes, int n_in,
                              void* d_out, int out_size) {
    const float* x     = (const float*)d_in[0];
    const float* dw    = (const float*)d_in[1];
    const float* gamma = (const float*)d_in[2];
    const float* beta  = (const float*)d_in[3];
    const float* ow    = (const float*)d_in[4];
    float* out = (float*)d_out;

    const int out_elems = R_TOT * D_DIM;
    int write_aux = (out_size >= out_elems + 2 * R_TOT) ? 1 : 0;
    size_t out_off = write_aux ? (size_t)(2 * R_TOT) : 0;

    cudaFuncSetAttribute(simmma_kernel, cudaFuncAttributeMaxDynamicSharedMemorySize, SIM_SMEM);

    norm_convert_kernel<<<R_TOT, 256>>>(x, 0);
    norm_convert_kernel<<<V_DIM, 256>>>(dw, 1);
    simmma_kernel<<<dim3(R_TOT / 128, NSPLIT), 256, SIM_SMEM>>>();
    rescore_kernel<<<R_TOT, 256>>>(x, dw, out, write_aux);
    ln_kernel<<<R_TOT, 256>>>(x, dw, gamma, beta);
    outgemm_kernel<<<dim3(R_TOT / BM, D_DIM / BN), 128>>>(ow, out + out_off);
}

// round 8
// speedup vs baseline: 9.0082x; 1.6657x over previous
#include <cuda_runtime.h>
#include <cuda_bf16.h>
#include <cstdint>

#define R_TOT 8192     // B*S
#define D_DIM 1024
#define V_DIM 16384
#define NSPLIT 8       // V splits (grid.y)
#define NCAND 16       // candidate slots per row: 8 splits x 2 warp-halves

// ---------------- device scratch ----------------
__device__ float g_inv_x[R_TOT];
__device__ float g_inv_d[V_DIM];
__device__ __nv_bfloat16 g_qbf[(size_t)R_TOT * D_DIM];   // normalized x, bf16
__device__ __nv_bfloat16 g_kbf[(size_t)V_DIM * D_DIM];   // normalized dict, bf16
__device__ float g_cv[R_TOT][NCAND][2];
__device__ int   g_ci[R_TOT][NCAND][2];
__device__ int   g_widx[R_TOT];
__device__ __nv_bfloat16 g_ehi[(size_t)R_TOT * D_DIM];   // e_ln hi
__device__ __nv_bfloat16 g_elo[(size_t)R_TOT * D_DIM];   // e_ln lo
__device__ __nv_bfloat16 g_whiT[(size_t)D_DIM * D_DIM];  // o_w^T hi
__device__ __nv_bfloat16 g_wloT[(size_t)D_DIM * D_DIM];  // o_w^T lo

__device__ __forceinline__ uint32_t smem_u32(const void* p) {
    uint32_t a;
    asm("{ .reg .u64 t; cvta.to.shared.u64 t, %1; cvt.u32.u64 %0, t; }" : "=r"(a) : "l"(p));
    return a;
}

// ---------------- block reduce (256 threads) ----------------
__device__ __forceinline__ float block_sum_256(float v, float* red) {
    #pragma unroll
    for (int o = 16; o; o >>= 1) v += __shfl_down_sync(0xffffffffu, v, o);
    int lane = threadIdx.x & 31, wid = threadIdx.x >> 5;
    __syncthreads();
    if (lane == 0) red[wid] = v;
    __syncthreads();
    float t = (threadIdx.x < 8) ? red[threadIdx.x] : 0.f;
    if (wid == 0) {
        #pragma unroll
        for (int o = 4; o; o >>= 1) t += __shfl_down_sync(0xffffffffu, t, o);
        if (lane == 0) red[0] = t;
    }
    __syncthreads();
    return red[0];
}

// ---------------- L2-normalize + bf16 convert ----------------
__global__ void norm_convert_kernel(const float* __restrict__ src, int which) {
    int row = blockIdx.x;
    const float* p = src + (size_t)row * D_DIM;
    int tid = threadIdx.x;
    float4 v = *(const float4*)(p + tid * 4);
    float s = v.x * v.x + v.y * v.y + v.z * v.z + v.w * v.w;
    __shared__ float red[32];
    float ss = block_sum_256(s, red);
    float inv = rsqrtf(fmaxf(ss, 1e-12f));
    __nv_bfloat16* dst = (which == 0 ? g_qbf : g_kbf) + (size_t)row * D_DIM + tid * 4;
    __nv_bfloat162 a = __floats2bfloat162_rn(v.x * inv, v.y * inv);
    __nv_bfloat162 b = __floats2bfloat162_rn(v.z * inv, v.w * inv);
    *(__nv_bfloat162*)(dst)     = a;
    *(__nv_bfloat162*)(dst + 2) = b;
    if (tid == 0) { if (which == 0) g_inv_x[row] = inv; else g_inv_d[row] = inv; }
}

// ---------------- common MMA machinery ----------------
#define STAGE_B 32768           // A 16KB + B 16KB
#define NSTAGE 3
#define MMA_SMEM (NSTAGE * STAGE_B)

#define CPA16(dst, src) \
    asm volatile("cp.async.cg.shared.global [%0], [%1], 16;" :: "r"(dst), "l"(src))
#define CPA_COMMIT() asm volatile("cp.async.commit_group;" ::: "memory")
#define CPA_WAIT1()  asm volatile("cp.async.wait_group 1;" ::: "memory")

#define LDMX4(r0, r1, r2, r3, addr) \
    asm volatile("ldmatrix.sync.aligned.m8n8.x4.shared.b16 {%0,%1,%2,%3}, [%4];" \
        : "=r"(r0), "=r"(r1), "=r"(r2), "=r"(r3) : "r"(addr))

#define MMA16816(d, a, b0, b1) \
    asm volatile("mma.sync.aligned.m16n8k16.row.col.f32.bf16.bf16.f32 " \
        "{%0,%1,%2,%3}, {%4,%5,%6,%7}, {%8,%9}, {%0,%1,%2,%3};" \
        : "+f"((d)[0]), "+f"((d)[1]), "+f"((d)[2]), "+f"((d)[3]) \
        : "r"((a)[0]), "r"((a)[1]), "r"((a)[2]), "r"((a)[3]), "r"(b0), "r"(b1))

#define INSERT(q, v, ix) do { \
    if ((v) > tv1[q] || ((v) == tv1[q] && (ix) < ti1[q])) { \
        tv2[q] = tv1[q]; ti2[q] = ti1[q]; tv1[q] = (v); ti1[q] = (ix); \
    } else if ((v) > tv2[q] || ((v) == tv2[q] && (ix) < ti2[q])) { \
        tv2[q] = (v); ti2[q] = (ix); \
    } } while (0)

// shared loader mapping: 4 x 16B per operand per chunk, XOR-swizzled
#define LOADER_SETUP() \
    int lrow[4], lkg[4]; uint32_t ldst[4]; \
    _Pragma("unroll") \
    for (int i = 0; i < 4; i++) { \
        int u = tid + i * 256; \
        lrow[i] = u >> 3; lkg[i] = u & 7; \
        ldst[i] = (uint32_t)(lrow[i] * 128 + ((lkg[i] ^ (lrow[i] & 7)) << 4)); \
    }

#define LDM_SETUP() \
    int a_row[2], b_row[4]; int a_kgb, b_kgb; \
    { \
        a_kgb = lane >> 4; \
        a_row[0] = wm + (lane & 15); \
        a_row[1] = wm + 16 + (lane & 15); \
        int bg = lane >> 3; \
        b_kgb = bg & 1; \
        _Pragma("unroll") \
        for (int p = 0; p < 4; p++) \
            b_row[p] = wn + (p * 2 + (bg >> 1)) * 8 + (lane & 7); \
    }

// one k64 chunk of MMAs from stage base aS (A) / bS (B)
#define COMPUTE_CHUNK(aS, bS) \
    _Pragma("unroll") \
    for (int ks = 0; ks < 4; ks++) { \
        uint32_t a[2][4]; \
        _Pragma("unroll") \
        for (int mt = 0; mt < 2; mt++) { \
            int kg = ks * 2 + a_kgb; \
            uint32_t addr = (aS) + a_row[mt] * 128 + ((kg ^ (a_row[mt] & 7)) << 4); \
            LDMX4(a[mt][0], a[mt][1], a[mt][2], a[mt][3], addr); \
        } \
        _Pragma("unroll") \
        for (int p = 0; p < 4; p++) { \
            uint32_t b[4]; \
            int kg = ks * 2 + b_kgb; \
            uint32_t addr = (bS) + b_row[p] * 128 + ((kg ^ (b_row[p] & 7)) << 4); \
            LDMX4(b[0], b[1], b[2], b[3], addr); \
            _Pragma("unroll") \
            for (int mt = 0; mt < 2; mt++) { \
                MMA16816(acc[mt][p * 2 + 0], a[mt], b[0], b[1]); \
                MMA16816(acc[mt][p * 2 + 1], a[mt], b[2], b[3]); \
            } \
        } \
    }

// ---------------- bf16 mma sim-GEMM + per-row top-2 ----------------
// CTA 128(M) x 128(N) per n-tile, 16 n-tiles per CTA, K=1024 in 64-wide chunks.
// Flat chunk stream g = nt*16 + kc, 3-stage cp.async ring, 1 sync per chunk.
__global__ void __launch_bounds__(256, 2)
simmma_kernel() {
    extern __shared__ char sm[];
    uint32_t sb = smem_u32(sm);
    const int tid = threadIdx.x, lane = tid & 31, w = tid >> 5;
    const int wm = (w & 3) * 32, wn = (w >> 2) * 64;
    const int rb = blockIdx.x * 128;
    const int cb = blockIdx.y * 2048;

    LOADER_SETUP();
    LDM_SETUP();

    float tv1[4], tv2[4]; int ti1[4], ti2[4];
    #pragma unroll
    for (int q = 0; q < 4; q++) { tv1[q] = -2.f; tv2[q] = -2.f; ti1[q] = 0; ti2[q] = 0; }

    const __nv_bfloat16* Ab = g_qbf + (size_t)rb * D_DIM;
    const __nv_bfloat16* Bb = g_kbf + (size_t)cb * D_DIM;

    // prologue: chunks 0,1 -> stages 0,1
    #pragma unroll
    for (int h = 0; h < 2; h++) {
        uint32_t stg = sb + h * STAGE_B;   // stage h
        #pragma unroll
        for (int i = 0; i < 4; i++) {
            CPA16(stg + ldst[i],         Ab + (size_t)lrow[i] * D_DIM + h * 64 + lkg[i] * 8);
            CPA16(stg + 16384 + ldst[i], Bb + (size_t)lrow[i] * D_DIM + h * 64 + lkg[i] * 8);
        }
        CPA_COMMIT();
    }
    CPA_WAIT1();
    __syncthreads();

    float acc[2][8][4];
    int st = 0;                 // stage of chunk g
    #pragma unroll 1
    for (int g = 0; g < 256; g++) {
        int kc = g & 15, nt = g >> 4;
        if (kc == 0) {
            #pragma unroll
            for (int mt = 0; mt < 2; mt++)
                #pragma unroll
                for (int j = 0; j < 8; j++)
                    #pragma unroll
                    for (int c = 0; c < 4; c++) acc[mt][j][c] = 0.f;
        }
        uint32_t aS = sb + st * STAGE_B;
        uint32_t bS = aS + 16384;
        COMPUTE_CHUNK(aS, bS);
        if (kc == 15) {
            int colbase = cb + nt * 128 + wn + (lane & 3) * 2;
            #pragma unroll
            for (int mt = 0; mt < 2; mt++)
                #pragma unroll
                for (int h2 = 0; h2 < 2; h2++) {
                    int q = mt * 2 + h2;
                    #pragma unroll
                    for (int j = 0; j < 8; j++) {
                        float v0 = acc[mt][j][h2 * 2 + 0];
                        float v1 = acc[mt][j][h2 * 2 + 1];
                        int c0 = colbase + j * 8;
                        INSERT(q, v0, c0);
                        INSERT(q, v1, c0 + 1);
                    }
                }
        }
        // issue chunk g+2 into stage (st+2)%3
        int h = g + 2;
        if (h < 256) {
            int kch = h & 15, nth = h >> 4;
            int sti = st + 2; if (sti >= 3) sti -= 3;
            uint32_t stg = sb + sti * STAGE_B;
            const __nv_bfloat16* Ac = Ab + kch * 64;
            const __nv_bfloat16* Bc = Bb + (size_t)(nth * 128) * D_DIM + kch * 64;
            #pragma unroll
            for (int i = 0; i < 4; i++) {
                CPA16(stg + ldst[i],         Ac + (size_t)lrow[i] * D_DIM + lkg[i] * 8);
                CPA16(stg + 16384 + ldst[i], Bc + (size_t)lrow[i] * D_DIM + lkg[i] * 8);
            }
        }
        CPA_COMMIT();
        CPA_WAIT1();
        __syncthreads();
        st++; if (st >= 3) st = 0;
    }

    // merge top-2 across the 4 lanes of each quad
    #pragma unroll
    for (int off = 1; off <= 2; off <<= 1) {
        #pragma unroll
        for (int q = 0; q < 4; q++) {
            float ov1 = __shfl_xor_sync(0xffffffffu, tv1[q], off);
            int   oi1 = __shfl_xor_sync(0xffffffffu, ti1[q], off);
            float ov2 = __shfl_xor_sync(0xffffffffu, tv2[q], off);
            int   oi2 = __shfl_xor_sync(0xffffffffu, ti2[q], off);
            INSERT(q, ov1, oi1);
            INSERT(q, ov2, oi2);
        }
    }
    if ((lane & 3) == 0) {
        int slot = blockIdx.y * 2 + (w >> 2);
        #pragma unroll
        for (int q = 0; q < 4; q++) {
            int row = rb + wm + (q >> 1) * 16 + (q & 1) * 8 + (lane >> 2);
            g_cv[row][slot][0] = tv1[q]; g_ci[row][slot][0] = ti1[q];
            g_cv[row][slot][1] = tv2[q]; g_ci[row][slot][1] = ti2[q];
        }
    }
}

// ---------------- exact fp32 rescore of candidates ----------------
__global__ void rescore_kernel(const float* __restrict__ X, const float* __restrict__ Dw,
                               float* __restrict__ out, int write_aux) {
    int row = blockIdx.x;
    int tid = threadIdx.x;
    __shared__ float sv[32]; __shared__ int si[32];
    __shared__ float red[32];
    __shared__ float s_vmax, s_best; __shared__ int s_bidx;
    if (tid < 32) { sv[tid] = g_cv[row][tid >> 1][tid & 1]; si[tid] = g_ci[row][tid >> 1][tid & 1]; }
    __syncthreads();
    if (tid == 0) {
        float vm = -9.f;
        for (int t = 0; t < 32; t++) vm = fmaxf(vm, sv[t]);
        s_vmax = vm; s_best = -9.f; s_bidx = 0x7FFFFFFF;
    }
    __syncthreads();
    float inva = g_inv_x[row];
    const float4* xr = (const float4*)(X + (size_t)row * D_DIM);
    float4 xv = xr[tid];
    for (int c = 0; c < 32; c++) {
        if (sv[c] < s_vmax - 1e-3f) continue;
        int idx = si[c];
        const float4* dr = (const float4*)(Dw + (size_t)idx * D_DIM);
        float4 dv = dr[tid];
        float part = xv.x * dv.x + xv.y * dv.y + xv.z * dv.z + xv.w * dv.w;
        float tot = block_sum_256(part, red);
        if (tid == 0) {
            float sim = tot * inva * g_inv_d[idx];
            if (sim > s_best || (sim == s_best && idx < s_bidx)) { s_best = sim; s_bidx = idx; }
        }
        __syncthreads();
    }
    if (tid == 0) {
        g_widx[row] = s_bidx;
        if (write_aux) { out[row] = (float)s_bidx; out[R_TOT + row] = s_best; }
    }
}

// ---------------- STE + LayerNorm -> split bf16 hi/lo ----------------
__global__ void ln_kernel(const float* __restrict__ X, const float* __restrict__ Dw,
                          const float* __restrict__ gamma, const float* __restrict__ beta) {
    int row = blockIdx.x;
    __shared__ float red[32];
    int idx = g_widx[row];
    const float* xr = X + (size_t)row * D_DIM;
    const float* zr = Dw + (size_t)idx * D_DIM;
    int tid = threadIdx.x;
    float ev[4];
    float s = 0.f;
    #pragma unroll
    for (int t = 0; t < 4; t++) {
        int j = t * 256 + tid;
        float xv = xr[j], zv = zr[j];
        ev[t] = (zv - xv) + xv;
        s += ev[t];
    }
    float mu = block_sum_256(s, red) * (1.0f / D_DIM);
    float ss = 0.f;
    #pragma unroll
    for (int t = 0; t < 4; t++) { float d = ev[t] - mu; ss += d * d; }
    float var = block_sum_256(ss, red) * (1.0f / D_DIM);
    float rsig = rsqrtf(var + 1e-6f);
    #pragma unroll
    for (int t = 0; t < 4; t++) {
        int j = t * 256 + tid;
        float v = (ev[t] - mu) * rsig * gamma[j] + beta[j];
        __nv_bfloat16 hi = __float2bfloat16(v);
        float lo = v - __bfloat162float(hi);
        size_t off = (size_t)row * D_DIM + j;
        g_ehi[off] = hi;
        g_elo[off] = __float2bfloat16(lo);
    }
}

// ---------------- o_w transpose + hi/lo split ----------------
__global__ void splitw_kernel(const float* __restrict__ W) {
    __shared__ float tile[32][33];
    int bk = blockIdx.x * 32, bn = blockIdx.y * 32;
    int tx = threadIdx.x, ty = threadIdx.y;  // 32 x 8
    #pragma unroll
    for (int r = 0; r < 32; r += 8)
        tile[ty + r][tx] = W[(size_t)(bk + ty + r) * D_DIM + bn + tx];
    __syncthreads();
    #pragma unroll
    for (int r = 0; r < 32; r += 8) {
        float v = tile[tx][ty + r];              // = W[bk+tx][bn+ty+r]
        __nv_bfloat16 hi = __float2bfloat16(v);
        float lo = v - __bfloat162float(hi);
        size_t off = (size_t)(bn + ty + r) * D_DIM + bk + tx;   // wT[n][k]
        g_whiT[off] = hi;
        g_wloT[off] = __float2bfloat16(lo);
    }
}

// ---------------- output projection: 3-term bf16 split GEMM ----------------
// out[m][n] = sum over K_eff = 3*1024: [ehi|ehi|elo] x [whi|wlo|whi]
__global__ void __launch_bounds__(256, 2)
outmma_kernel(float* __restrict__ Out) {
    extern __shared__ char sm[];
    uint32_t sb = smem_u32(sm);
    const int tid = threadIdx.x, lane = tid & 31, w = tid >> 5;
    const int wm = (w & 3) * 32, wn = (w >> 2) * 64;
    const int rb = blockIdx.x * 128;
    const int cbN = blockIdx.y * 128;

    LOADER_SETUP();
    LDM_SETUP();

    const int NCH = 48;

    // chunk h source pointers
    auto a_src = [&](int h) -> const __nv_bfloat16* {
        int seg = h >> 4, kc = h & 15;
        const __nv_bfloat16* base = (seg < 2) ? g_ehi : g_elo;
        return base + (size_t)rb * D_DIM + kc * 64;
    };
    auto b_src = [&](int h) -> const __nv_bfloat16* {
        int seg = h >> 4, kc = h & 15;
        const __nv_bfloat16* base = (seg == 1) ? g_wloT : g_whiT;
        return base + (size_t)cbN * D_DIM + kc * 64;
    };

    #pragma unroll
    for (int h = 0; h < 2; h++) {
        uint32_t stg = sb + h * STAGE_B;
        const __nv_bfloat16* Ac = a_src(h);
        const __nv_bfloat16* Bc = b_src(h);
        #pragma unroll
        for (int i = 0; i < 4; i++) {
            CPA16(stg + ldst[i],         Ac + (size_t)lrow[i] * D_DIM + lkg[i] * 8);
            CPA16(stg + 16384 + ldst[i], Bc + (size_t)lrow[i] * D_DIM + lkg[i] * 8);
        }
        CPA_COMMIT();
    }
    CPA_WAIT1();
    __syncthreads();

    float acc[2][8][4];
    #pragma unroll
    for (int mt = 0; mt < 2; mt++)
        #pragma unroll
        for (int j = 0; j < 8; j++)
            #pragma unroll
            for (int c = 0; c < 4; c++) acc[mt][j][c] = 0.f;

    int st = 0;
    #pragma unroll 1
    for (int g = 0; g < NCH; g++) {
        uint32_t aS = sb + st * STAGE_B;
        uint32_t bS = aS + 16384;
        COMPUTE_CHUNK(aS, bS);
        int h = g + 2;
        if (h < NCH) {
            int sti = st + 2; if (sti >= 3) sti -= 3;
            uint32_t stg = sb + sti * STAGE_B;
            const __nv_bfloat16* Ac = a_src(h);
            const __nv_bfloat16* Bc = b_src(h);
            #pragma unroll
            for (int i = 0; i < 4; i++) {
                CPA16(stg + ldst[i],         Ac + (size_t)lrow[i] * D_DIM + lkg[i] * 8);
                CPA16(stg + 16384 + ldst[i], Bc + (size_t)lrow[i] * D_DIM + lkg[i] * 8);
            }
        }
        CPA_COMMIT();
        CPA_WAIT1();
        __syncthreads();
        st++; if (st >= 3) st = 0;
    }

    // epilogue: write fp32 results
    #pragma unroll
    for (int mt = 0; mt < 2; mt++) {
        int row0 = rb + wm + mt * 16 + (lane >> 2);
        #pragma unroll
        for (int j = 0; j < 8; j++) {
            int col = cbN + wn + j * 8 + (lane & 3) * 2;
            *(float2*)(Out + (size_t)row0 * D_DIM + col) = make_float2(acc[mt][j][0], acc[mt][j][1]);
            *(float2*)(Out + (size_t)(row0 + 8) * D_DIM + col) = make_float2(acc[mt][j][2], acc[mt][j][3]);
        }
    }
}

extern "C" void kernel_launch(void* const* d_in, const int* in_sizes, int n_in,
                              void* d_out, int out_size) {
    const float* x     = (const float*)d_in[0];
    const float* dw    = (const float*)d_in[1];
    const float* gamma = (const float*)d_in[2];
    const float* beta  = (const float*)d_in[3];
    const float* ow    = (const float*)d_in[4];
    float* out = (float*)d_out;

    const int out_elems = R_TOT * D_DIM;
    int write_aux = (out_size >= out_elems + 2 * R_TOT) ? 1 : 0;
    size_t out_off = write_aux ? (size_t)(2 * R_TOT) : 0;

    cudaFuncSetAttribute(simmma_kernel, cudaFuncAttributeMaxDynamicSharedMemorySize, MMA_SMEM);
    cudaFuncSetAttribute(outmma_kernel, cudaFuncAttributeMaxDynamicSharedMemorySize, MMA_SMEM);

    norm_convert_kernel<<<R_TOT, 256>>>(x, 0);
    norm_convert_kernel<<<V_DIM, 256>>>(dw, 1);
    splitw_kernel<<<dim3(D_DIM / 32, D_DIM / 32), dim3(32, 8)>>>(ow);
    simmma_kernel<<<dim3(R_TOT / 128, NSPLIT), 256, MMA_SMEM>>>();
    rescore_kernel<<<R_TOT, 256>>>(x, dw, out, write_aux);
    ln_kernel<<<R_TOT, 256>>>(x, dw, gamma, beta);
    outmma_kernel<<<dim3(R_TOT / 128, D_DIM / 128), 256, MMA_SMEM>>>(out + out_off);
}

// round 9
// speedup vs baseline: 9.8647x; 1.0951x over previous
#include <cuda_runtime.h>
#include <cuda_bf16.h>
#include <cstdint>

#define R_TOT 8192     // B*S
#define D_DIM 1024
#define V_DIM 16384
#define NGRP  64       // col groups (grid.y), 256 cols each
#define NCAND 128      // candidate slots per row: 64 groups x 2 warp-halves

// ---------------- device scratch ----------------
__device__ float g_inv_x[R_TOT];
__device__ float g_inv_d[V_DIM];
__device__ __nv_bfloat16 g_qbf[(size_t)R_TOT * D_DIM];   // normalized x, bf16
__device__ __nv_bfloat16 g_kbf[(size_t)V_DIM * D_DIM];   // normalized dict, bf16
__device__ float g_cv[R_TOT][NCAND][2];
__device__ int   g_ci[R_TOT][NCAND][2];
__device__ int   g_widx[R_TOT];
__device__ __nv_bfloat16 g_ehi[(size_t)R_TOT * D_DIM];   // e_ln hi
__device__ __nv_bfloat16 g_elo[(size_t)R_TOT * D_DIM];   // e_ln lo
__device__ __nv_bfloat16 g_whiT[(size_t)D_DIM * D_DIM];  // o_w^T hi
__device__ __nv_bfloat16 g_wloT[(size_t)D_DIM * D_DIM];  // o_w^T lo

__device__ __forceinline__ uint32_t smem_u32(const void* p) {
    uint32_t a;
    asm("{ .reg .u64 t; cvta.to.shared.u64 t, %1; cvt.u32.u64 %0, t; }" : "=r"(a) : "l"(p));
    return a;
}

// ---------------- block reduce (256 threads) ----------------
__device__ __forceinline__ float block_sum_256(float v, float* red) {
    #pragma unroll
    for (int o = 16; o; o >>= 1) v += __shfl_down_sync(0xffffffffu, v, o);
    int lane = threadIdx.x & 31, wid = threadIdx.x >> 5;
    __syncthreads();
    if (lane == 0) red[wid] = v;
    __syncthreads();
    float t = (threadIdx.x < 8) ? red[threadIdx.x] : 0.f;
    if (wid == 0) {
        #pragma unroll
        for (int o = 4; o; o >>= 1) t += __shfl_down_sync(0xffffffffu, t, o);
        if (lane == 0) red[0] = t;
    }
    __syncthreads();
    return red[0];
}

__device__ __forceinline__ float block_max_256(float v, float* red) {
    #pragma unroll
    for (int o = 16; o; o >>= 1) v = fmaxf(v, __shfl_xor_sync(0xffffffffu, v, o));
    int lane = threadIdx.x & 31, wid = threadIdx.x >> 5;
    __syncthreads();
    if (lane == 0) red[wid] = v;
    __syncthreads();
    float t = (threadIdx.x < 8) ? red[threadIdx.x] : -9.f;
    if (wid == 0) {
        #pragma unroll
        for (int o = 4; o; o >>= 1) t = fmaxf(t, __shfl_xor_sync(0xffffffffu, t, o));
        if (lane == 0) red[0] = t;
    }
    __syncthreads();
    return red[0];
}

// ---------------- L2-normalize + bf16 convert ----------------
__global__ void norm_convert_kernel(const float* __restrict__ src, int which) {
    int row = blockIdx.x;
    const float* p = src + (size_t)row * D_DIM;
    int tid = threadIdx.x;
    float4 v = *(const float4*)(p + tid * 4);
    float s = v.x * v.x + v.y * v.y + v.z * v.z + v.w * v.w;
    __shared__ float red[32];
    float ss = block_sum_256(s, red);
    float inv = rsqrtf(fmaxf(ss, 1e-12f));
    __nv_bfloat16* dst = (which == 0 ? g_qbf : g_kbf) + (size_t)row * D_DIM + tid * 4;
    __nv_bfloat162 a = __floats2bfloat162_rn(v.x * inv, v.y * inv);
    __nv_bfloat162 b = __floats2bfloat162_rn(v.z * inv, v.w * inv);
    *(__nv_bfloat162*)(dst)     = a;
    *(__nv_bfloat162*)(dst + 2) = b;
    if (tid == 0) { if (which == 0) g_inv_x[row] = inv; else g_inv_d[row] = inv; }
}

// ---------------- common MMA machinery ----------------
#define STAGE_B 32768           // A 16KB + B 16KB
#define NSTAGE 3
#define MMA_SMEM (NSTAGE * STAGE_B)

#define CPA16(dst, src) \
    asm volatile("cp.async.cg.shared.global [%0], [%1], 16;" :: "r"(dst), "l"(src))
#define CPA_COMMIT() asm volatile("cp.async.commit_group;" ::: "memory")
#define CPA_WAIT1()  asm volatile("cp.async.wait_group 1;" ::: "memory")

#define LDMX4(r0, r1, r2, r3, addr) \
    asm volatile("ldmatrix.sync.aligned.m8n8.x4.shared.b16 {%0,%1,%2,%3}, [%4];" \
        : "=r"(r0), "=r"(r1), "=r"(r2), "=r"(r3) : "r"(addr))

#define MMA16816(d, a, b0, b1) \
    asm volatile("mma.sync.aligned.m16n8k16.row.col.f32.bf16.bf16.f32 " \
        "{%0,%1,%2,%3}, {%4,%5,%6,%7}, {%8,%9}, {%0,%1,%2,%3};" \
        : "+f"((d)[0]), "+f"((d)[1]), "+f"((d)[2]), "+f"((d)[3]) \
        : "r"((a)[0]), "r"((a)[1]), "r"((a)[2]), "r"((a)[3]), "r"(b0), "r"(b1))

#define INSERT(q, v, ix) do { \
    if ((v) > tv1[q] || ((v) == tv1[q] && (ix) < ti1[q])) { \
        tv2[q] = tv1[q]; ti2[q] = ti1[q]; tv1[q] = (v); ti1[q] = (ix); \
    } else if ((v) > tv2[q] || ((v) == tv2[q] && (ix) < ti2[q])) { \
        tv2[q] = (v); ti2[q] = (ix); \
    } } while (0)

#define LOADER_SETUP() \
    int lrow[4], lkg[4]; uint32_t ldst[4]; \
    _Pragma("unroll") \
    for (int i = 0; i < 4; i++) { \
        int u = tid + i * 256; \
        lrow[i] = u >> 3; lkg[i] = u & 7; \
        ldst[i] = (uint32_t)(lrow[i] * 128 + ((lkg[i] ^ (lrow[i] & 7)) << 4)); \
    }

#define LDM_SETUP() \
    int a_row[2], b_row[4]; int a_kgb, b_kgb; \
    { \
        a_kgb = lane >> 4; \
        a_row[0] = wm + (lane & 15); \
        a_row[1] = wm + 16 + (lane & 15); \
        int bg = lane >> 3; \
        b_kgb = bg & 1; \
        _Pragma("unroll") \
        for (int p = 0; p < 4; p++) \
            b_row[p] = wn + (p * 2 + (bg >> 1)) * 8 + (lane & 7); \
    }

#define COMPUTE_CHUNK(aS, bS) \
    _Pragma("unroll") \
    for (int ks = 0; ks < 4; ks++) { \
        uint32_t a[2][4]; \
        _Pragma("unroll") \
        for (int mt = 0; mt < 2; mt++) { \
            int kg = ks * 2 + a_kgb; \
            uint32_t addr = (aS) + a_row[mt] * 128 + ((kg ^ (a_row[mt] & 7)) << 4); \
            LDMX4(a[mt][0], a[mt][1], a[mt][2], a[mt][3], addr); \
        } \
        _Pragma("unroll") \
        for (int p = 0; p < 4; p++) { \
            uint32_t b[4]; \
            int kg = ks * 2 + b_kgb; \
            uint32_t addr = (bS) + b_row[p] * 128 + ((kg ^ (b_row[p] & 7)) << 4); \
            LDMX4(b[0], b[1], b[2], b[3], addr); \
            _Pragma("unroll") \
            for (int mt = 0; mt < 2; mt++) { \
                MMA16816(acc[mt][p * 2 + 0], a[mt], b[0], b[1]); \
                MMA16816(acc[mt][p * 2 + 1], a[mt], b[2], b[3]); \
            } \
        } \
    }

// ---------------- bf16 mma sim-GEMM + per-row top-2 ----------------
// grid (64 m-tiles, 64 col-groups). Each CTA: 128 rows x 256 cols (2 n-tiles),
// 32 flat K-chunks, 3-stage cp.async ring, 1 sync per chunk.
__global__ void __launch_bounds__(256, 2)
simmma_kernel() {
    extern __shared__ char sm[];
    uint32_t sb = smem_u32(sm);
    const int tid = threadIdx.x, lane = tid & 31, w = tid >> 5;
    const int wm = (w & 3) * 32, wn = (w >> 2) * 64;
    const int rb = blockIdx.x * 128;
    const int cb = blockIdx.y * 256;

    LOADER_SETUP();
    LDM_SETUP();

    float tv1[4], tv2[4]; int ti1[4], ti2[4];
    #pragma unroll
    for (int q = 0; q < 4; q++) { tv1[q] = -2.f; tv2[q] = -2.f; ti1[q] = 0; ti2[q] = 0; }

    const __nv_bfloat16* Ab = g_qbf + (size_t)rb * D_DIM;
    const __nv_bfloat16* Bb = g_kbf + (size_t)cb * D_DIM;

    // prologue: chunks 0,1 -> stages 0,1  (chunk h: nt = h>>4, kc = h&15)
    #pragma unroll
    for (int h = 0; h < 2; h++) {
        uint32_t stg = sb + h * STAGE_B;
        #pragma unroll
        for (int i = 0; i < 4; i++) {
            CPA16(stg + ldst[i],         Ab + (size_t)lrow[i] * D_DIM + h * 64 + lkg[i] * 8);
            CPA16(stg + 16384 + ldst[i], Bb + (size_t)lrow[i] * D_DIM + h * 64 + lkg[i] * 8);
        }
        CPA_COMMIT();
    }
    CPA_WAIT1();
    __syncthreads();

    float acc[2][8][4];
    int st = 0;
    #pragma unroll 1
    for (int g = 0; g < 32; g++) {
        int kc = g & 15, nt = g >> 4;
        if (kc == 0) {
            #pragma unroll
            for (int mt = 0; mt < 2; mt++)
                #pragma unroll
                for (int j = 0; j < 8; j++)
                    #pragma unroll
                    for (int c = 0; c < 4; c++) acc[mt][j][c] = 0.f;
        }
        uint32_t aS = sb + st * STAGE_B;
        uint32_t bS = aS + 16384;
        COMPUTE_CHUNK(aS, bS);
        if (kc == 15) {
            int colbase = cb + nt * 128 + wn + (lane & 3) * 2;
            #pragma unroll
            for (int mt = 0; mt < 2; mt++)
                #pragma unroll
                for (int h2 = 0; h2 < 2; h2++) {
                    int q = mt * 2 + h2;
                    #pragma unroll
                    for (int j = 0; j < 8; j++) {
                        float v0 = acc[mt][j][h2 * 2 + 0];
                        float v1 = acc[mt][j][h2 * 2 + 1];
                        int c0 = colbase + j * 8;
                        INSERT(q, v0, c0);
                        INSERT(q, v1, c0 + 1);
                    }
                }
        }
        int h = g + 2;
        if (h < 32) {
            int kch = h & 15, nth = h >> 4;
            int sti = st + 2; if (sti >= 3) sti -= 3;
            uint32_t stg = sb + sti * STAGE_B;
            const __nv_bfloat16* Ac = Ab + kch * 64;
            const __nv_bfloat16* Bc = Bb + (size_t)(nth * 128) * D_DIM + kch * 64;
            #pragma unroll
            for (int i = 0; i < 4; i++) {
                CPA16(stg + ldst[i],         Ac + (size_t)lrow[i] * D_DIM + lkg[i] * 8);
                CPA16(stg + 16384 + ldst[i], Bc + (size_t)lrow[i] * D_DIM + lkg[i] * 8);
            }
        }
        CPA_COMMIT();
        CPA_WAIT1();
        __syncthreads();
        st++; if (st >= 3) st = 0;
    }

    // merge top-2 across the 4 lanes of each quad
    #pragma unroll
    for (int off = 1; off <= 2; off <<= 1) {
        #pragma unroll
        for (int q = 0; q < 4; q++) {
            float ov1 = __shfl_xor_sync(0xffffffffu, tv1[q], off);
            int   oi1 = __shfl_xor_sync(0xffffffffu, ti1[q], off);
            float ov2 = __shfl_xor_sync(0xffffffffu, tv2[q], off);
            int   oi2 = __shfl_xor_sync(0xffffffffu, ti2[q], off);
            INSERT(q, ov1, oi1);
            INSERT(q, ov2, oi2);
        }
    }
    if ((lane & 3) == 0) {
        int slot = blockIdx.y * 2 + (w >> 2);
        #pragma unroll
        for (int q = 0; q < 4; q++) {
            int row = rb + wm + (q >> 1) * 16 + (q & 1) * 8 + (lane >> 2);
            g_cv[row][slot][0] = tv1[q]; g_ci[row][slot][0] = ti1[q];
            g_cv[row][slot][1] = tv2[q]; g_ci[row][slot][1] = ti2[q];
        }
    }
}

// ---------------- exact fp32 rescore of candidates ----------------
// 256 candidate entries/row; parallel margin-compaction to <=32 survivors.
__global__ void rescore_kernel(const float* __restrict__ X, const float* __restrict__ Dw,
                               float* __restrict__ out, int write_aux) {
    int row = blockIdx.x;
    int tid = threadIdx.x;
    __shared__ float red[32];
    __shared__ int cl[32];
    __shared__ int s_cnt;
    __shared__ float s_best; __shared__ int s_bidx;
    float mv = g_cv[row][tid >> 1][tid & 1];
    int   mi = g_ci[row][tid >> 1][tid & 1];
    float vmax = block_max_256(mv, red);
    if (tid == 0) { s_cnt = 0; s_best = -9.f; s_bidx = 0x7FFFFFFF; }
    __syncthreads();
    if (mv >= vmax - 1e-3f) {
        int pos = atomicAdd(&s_cnt, 1);
        if (pos < 32) cl[pos] = mi;
    }
    __syncthreads();
    int cnt = s_cnt; if (cnt > 32) cnt = 32;
    float inva = g_inv_x[row];
    const float4* xr = (const float4*)(X + (size_t)row * D_DIM);
    float4 xv = xr[tid];
    for (int c = 0; c < cnt; c++) {
        int idx = cl[c];
        const float4* dr = (const float4*)(Dw + (size_t)idx * D_DIM);
        float4 dv = dr[tid];
        float part = xv.x * dv.x + xv.y * dv.y + xv.z * dv.z + xv.w * dv.w;
        float tot = block_sum_256(part, red);
        if (tid == 0) {
            float sim = tot * inva * g_inv_d[idx];
            if (sim > s_best || (sim == s_best && idx < s_bidx)) { s_best = sim; s_bidx = idx; }
        }
        __syncthreads();
    }
    if (tid == 0) {
        g_widx[row] = s_bidx;
        if (write_aux) { out[row] = (float)s_bidx; out[R_TOT + row] = s_best; }
    }
}

// ---------------- STE + LayerNorm -> split bf16 hi/lo ----------------
__global__ void ln_kernel(const float* __restrict__ X, const float* __restrict__ Dw,
                          const float* __restrict__ gamma, const float* __restrict__ beta) {
    int row = blockIdx.x;
    __shared__ float red[32];
    int idx = g_widx[row];
    const float* xr = X + (size_t)row * D_DIM;
    const float* zr = Dw + (size_t)idx * D_DIM;
    int tid = threadIdx.x;
    float ev[4];
    float s = 0.f;
    #pragma unroll
    for (int t = 0; t < 4; t++) {
        int j = t * 256 + tid;
        float xv = xr[j], zv = zr[j];
        ev[t] = (zv - xv) + xv;
        s += ev[t];
    }
    float mu = block_sum_256(s, red) * (1.0f / D_DIM);
    float ss = 0.f;
    #pragma unroll
    for (int t = 0; t < 4; t++) { float d = ev[t] - mu; ss += d * d; }
    float var = block_sum_256(ss, red) * (1.0f / D_DIM);
    float rsig = rsqrtf(var + 1e-6f);
    #pragma unroll
    for (int t = 0; t < 4; t++) {
        int j = t * 256 + tid;
        float v = (ev[t] - mu) * rsig * gamma[j] + beta[j];
        __nv_bfloat16 hi = __float2bfloat16(v);
        float lo = v - __bfloat162float(hi);
        size_t off = (size_t)row * D_DIM + j;
        g_ehi[off] = hi;
        g_elo[off] = __float2bfloat16(lo);
    }
}

// ---------------- o_w transpose + hi/lo split ----------------
__global__ void splitw_kernel(const float* __restrict__ W) {
    __shared__ float tile[32][33];
    int bk = blockIdx.x * 32, bn = blockIdx.y * 32;
    int tx = threadIdx.x, ty = threadIdx.y;  // 32 x 8
    #pragma unroll
    for (int r = 0; r < 32; r += 8)
        tile[ty + r][tx] = W[(size_t)(bk + ty + r) * D_DIM + bn + tx];
    __syncthreads();
    #pragma unroll
    for (int r = 0; r < 32; r += 8) {
        float v = tile[tx][ty + r];
        __nv_bfloat16 hi = __float2bfloat16(v);
        float lo = v - __bfloat162float(hi);
        size_t off = (size_t)(bn + ty + r) * D_DIM + bk + tx;
        g_whiT[off] = hi;
        g_wloT[off] = __float2bfloat16(lo);
    }
}

// ---------------- output projection: 3-term bf16 split GEMM ----------------
__global__ void __launch_bounds__(256, 2)
outmma_kernel(float* __restrict__ Out) {
    extern __shared__ char sm[];
    uint32_t sb = smem_u32(sm);
    const int tid = threadIdx.x, lane = tid & 31, w = tid >> 5;
    const int wm = (w & 3) * 32, wn = (w >> 2) * 64;
    const int rb = blockIdx.x * 128;
    const int cbN = blockIdx.y * 128;

    LOADER_SETUP();
    LDM_SETUP();

    const int NCH = 48;

    auto a_src = [&](int h) -> const __nv_bfloat16* {
        int seg = h >> 4, kc = h & 15;
        const __nv_bfloat16* base = (seg < 2) ? g_ehi : g_elo;
        return base + (size_t)rb * D_DIM + kc * 64;
    };
    auto b_src = [&](int h) -> const __nv_bfloat16* {
        int seg = h >> 4, kc = h & 15;
        const __nv_bfloat16* base = (seg == 1) ? g_wloT : g_whiT;
        return base + (size_t)cbN * D_DIM + kc * 64;
    };

    #pragma unroll
    for (int h = 0; h < 2; h++) {
        uint32_t stg = sb + h * STAGE_B;
        const __nv_bfloat16* Ac = a_src(h);
        const __nv_bfloat16* Bc = b_src(h);
        #pragma unroll
        for (int i = 0; i < 4; i++) {
            CPA16(stg + ldst[i],         Ac + (size_t)lrow[i] * D_DIM + lkg[i] * 8);
            CPA16(stg + 16384 + ldst[i], Bc + (size_t)lrow[i] * D_DIM + lkg[i] * 8);
        }
        CPA_COMMIT();
    }
    CPA_WAIT1();
    __syncthreads();

    float acc[2][8][4];
    #pragma unroll
    for (int mt = 0; mt < 2; mt++)
        #pragma unroll
        for (int j = 0; j < 8; j++)
            #pragma unroll
            for (int c = 0; c < 4; c++) acc[mt][j][c] = 0.f;

    int st = 0;
    #pragma unroll 1
    for (int g = 0; g < NCH; g++) {
        uint32_t aS = sb + st * STAGE_B;
        uint32_t bS = aS + 16384;
        COMPUTE_CHUNK(aS, bS);
        int h = g + 2;
        if (h < NCH) {
            int sti = st + 2; if (sti >= 3) sti -= 3;
            uint32_t stg = sb + sti * STAGE_B;
            const __nv_bfloat16* Ac = a_src(h);
            const __nv_bfloat16* Bc = b_src(h);
            #pragma unroll
            for (int i = 0; i < 4; i++) {
                CPA16(stg + ldst[i],         Ac + (size_t)lrow[i] * D_DIM + lkg[i] * 8);
                CPA16(stg + 16384 + ldst[i], Bc + (size_t)lrow[i] * D_DIM + lkg[i] * 8);
            }
        }
        CPA_COMMIT();
        CPA_WAIT1();
        __syncthreads();
        st++; if (st >= 3) st = 0;
    }

    #pragma unroll
    for (int mt = 0; mt < 2; mt++) {
        int row0 = rb + wm + mt * 16 + (lane >> 2);
        #pragma unroll
        for (int j = 0; j < 8; j++) {
            int col = cbN + wn + j * 8 + (lane & 3) * 2;
            *(float2*)(Out + (size_t)row0 * D_DIM + col) = make_float2(acc[mt][j][0], acc[mt][j][1]);
            *(float2*)(Out + (size_t)(row0 + 8) * D_DIM + col) = make_float2(acc[mt][j][2], acc[mt][j][3]);
        }
    }
}

extern "C" void kernel_launch(void* const* d_in, const int* in_sizes, int n_in,
                              void* d_out, int out_size) {
    const float* x     = (const float*)d_in[0];
    const float* dw    = (const float*)d_in[1];
    const float* gamma = (const float*)d_in[2];
    const float* beta  = (const float*)d_in[3];
    const float* ow    = (const float*)d_in[4];
    float* out = (float*)d_out;

    const int out_elems = R_TOT * D_DIM;
    int write_aux = (out_size >= out_elems + 2 * R_TOT) ? 1 : 0;
    size_t out_off = write_aux ? (size_t)(2 * R_TOT) : 0;

    cudaFuncSetAttribute(simmma_kernel, cudaFuncAttributeMaxDynamicSharedMemorySize, MMA_SMEM);
    cudaFuncSetAttribute(outmma_kernel, cudaFuncAttributeMaxDynamicSharedMemorySize, MMA_SMEM);

    norm_convert_kernel<<<R_TOT, 256>>>(x, 0);
    norm_convert_kernel<<<V_DIM, 256>>>(dw, 1);
    splitw_kernel<<<dim3(D_DIM / 32, D_DIM / 32), dim3(32, 8)>>>(ow);
    simmma_kernel<<<dim3(R_TOT / 128, NGRP), 256, MMA_SMEM>>>();
    rescore_kernel<<<R_TOT, 256>>>(x, dw, out, write_aux);
    ln_kernel<<<R_TOT, 256>>>(x, dw, gamma, beta);
    outmma_kernel<<<dim3(R_TOT / 128, D_DIM / 128), 256, MMA_SMEM>>>(out + out_off);
}